// round 1
// baseline (speedup 1.0000x reference)
#include <cuda_runtime.h>
#include <cuda_bf16.h>
#include <cstdint>

// Problem constants (fixed by the reference)
#define NUM_USER  200000
#define NUM_GROUP 50000
#define NN        (NUM_USER + NUM_GROUP)   // 250000
#define EDGES     4000000
#define DD        64
#define BB        8192
#define NF4       (NN * (DD / 4))          // number of float4 rows-slices = 4,000,000

// Scratch: 3 embedding buffers of 250000 x 64 fp32 = 64 MB each (192 MB total).
// __device__ globals are the sanctioned way to get scratch (no cudaMalloc allowed).
__device__ float g_cur[(size_t)NN * DD];
__device__ float g_nxt[(size_t)NN * DD];
__device__ float g_acc[(size_t)NN * DD];

// ---------------------------------------------------------------------------
// init: cur = acc = concat(user_table, group_table); nxt = 0
// ---------------------------------------------------------------------------
__global__ __launch_bounds__(256)
void init_kernel(const float4* __restrict__ ut, const float4* __restrict__ gt)
{
    int i = blockIdx.x * blockDim.x + threadIdx.x;  // float4 index
    if (i >= NF4) return;
    const int USER_F4 = NUM_USER * (DD / 4);
    float4 v = (i < USER_F4) ? ut[i] : gt[i - USER_F4];
    reinterpret_cast<float4*>(g_cur)[i] = v;
    reinterpret_cast<float4*>(g_acc)[i] = v;
    reinterpret_cast<float4*>(g_nxt)[i] = make_float4(0.f, 0.f, 0.f, 0.f);
}

// ---------------------------------------------------------------------------
// spmm: dst[rows[e]] += vals[e] * src[cols[e]]   (dst pre-zeroed)
// 16 threads per edge, one float4 lane each. 128-bit RED atomics.
// ---------------------------------------------------------------------------
__global__ __launch_bounds__(256)
void spmm_kernel(const float* __restrict__ src, float* __restrict__ dst,
                 const float* __restrict__ vals,
                 const int*   __restrict__ rows,
                 const int*   __restrict__ cols)
{
    int t = blockIdx.x * blockDim.x + threadIdx.x;
    int e    = t >> 4;
    int lane = t & 15;
    if (e >= EDGES) return;

    int   r = rows[e];
    int   c = cols[e];
    float v = vals[e];

    float4 x = reinterpret_cast<const float4*>(src + (size_t)c * DD)[lane];
    float4 y = make_float4(x.x * v, x.y * v, x.z * v, x.w * v);
    atomicAdd(reinterpret_cast<float4*>(dst + (size_t)r * DD) + lane, y);
}

// ---------------------------------------------------------------------------
// add_zero: acc += just_computed; zero the stale source buffer for reuse
// ---------------------------------------------------------------------------
__global__ __launch_bounds__(256)
void add_zero_kernel(const float4* __restrict__ fresh,
                     float4* __restrict__ acc,
                     float4* __restrict__ tozero)
{
    int i = blockIdx.x * blockDim.x + threadIdx.x;
    if (i >= NF4) return;
    float4 a = acc[i];
    float4 b = fresh[i];
    acc[i]    = make_float4(a.x + b.x, a.y + b.y, a.z + b.z, a.w + b.w);
    tozero[i] = make_float4(0.f, 0.f, 0.f, 0.f);
}

// ---------------------------------------------------------------------------
// gather: six (8192, 64) outputs, concatenated in d_out
//   0: acc[user]/4   1: acc[NUM_USER+pos]/4   2: acc[NUM_USER+neg]/4
//   3: user_table[user]   4: group_table[pos]   5: group_table[neg]
// ---------------------------------------------------------------------------
__global__ __launch_bounds__(256)
void gather_kernel(const float4* __restrict__ ut, const float4* __restrict__ gt,
                   const int* __restrict__ ui, const int* __restrict__ pg,
                   const int* __restrict__ ng, float4* __restrict__ out)
{
    int t = blockIdx.x * blockDim.x + threadIdx.x;
    if (t >= BB * 16) return;
    int b    = t >> 4;
    int lane = t & 15;

    int u = ui[b];
    int p = pg[b];
    int n = ng[b];

    const float4* acc4 = reinterpret_cast<const float4*>(g_acc);
    float4 a0 = acc4[(size_t)u * 16 + lane];
    float4 a1 = acc4[((size_t)NUM_USER + p) * 16 + lane];
    float4 a2 = acc4[((size_t)NUM_USER + n) * 16 + lane];

    const float s = 0.25f;  // 1/(L+1)
    out[((size_t)0 * BB + b) * 16 + lane] = make_float4(a0.x*s, a0.y*s, a0.z*s, a0.w*s);
    out[((size_t)1 * BB + b) * 16 + lane] = make_float4(a1.x*s, a1.y*s, a1.z*s, a1.w*s);
    out[((size_t)2 * BB + b) * 16 + lane] = make_float4(a2.x*s, a2.y*s, a2.z*s, a2.w*s);
    out[((size_t)3 * BB + b) * 16 + lane] = ut[(size_t)u * 16 + lane];
    out[((size_t)4 * BB + b) * 16 + lane] = gt[(size_t)p * 16 + lane];
    out[((size_t)5 * BB + b) * 16 + lane] = gt[(size_t)n * 16 + lane];
}

// ---------------------------------------------------------------------------
// launch
// ---------------------------------------------------------------------------
extern "C" void kernel_launch(void* const* d_in, const int* in_sizes, int n_in,
                              void* d_out, int out_size)
{
    const float* user_table  = (const float*)d_in[0];
    const float* group_table = (const float*)d_in[1];
    const float* adj_vals    = (const float*)d_in[2];
    const int*   rows        = (const int*)  d_in[3];
    const int*   cols        = (const int*)  d_in[4];
    const int*   user_inputs = (const int*)  d_in[5];
    const int*   pos_groups  = (const int*)  d_in[6];
    const int*   neg_groups  = (const int*)  d_in[7];

    float* cur = nullptr, * nxt = nullptr, * acc = nullptr;
    cudaGetSymbolAddress((void**)&cur, g_cur);
    cudaGetSymbolAddress((void**)&nxt, g_nxt);
    cudaGetSymbolAddress((void**)&acc, g_acc);

    const int TB = 256;
    const int grid_full  = (NF4 + TB - 1) / TB;           // 15625 blocks... (4M/256)
    const int grid_spmm  = (EDGES * 16 + TB - 1) / TB;    // 250000 blocks
    const int grid_gath  = (BB * 16 + TB - 1) / TB;

    // init: cur = acc = emb0, nxt = 0
    init_kernel<<<grid_full, TB>>>((const float4*)user_table, (const float4*)group_table);

    // Layer 1: nxt = A*cur; acc += nxt; zero cur
    spmm_kernel<<<grid_spmm, TB>>>(cur, nxt, adj_vals, rows, cols);
    add_zero_kernel<<<grid_full, TB>>>((const float4*)nxt, (float4*)acc, (float4*)cur);

    // Layer 2: cur = A*nxt; acc += cur; zero nxt
    spmm_kernel<<<grid_spmm, TB>>>(nxt, cur, adj_vals, rows, cols);
    add_zero_kernel<<<grid_full, TB>>>((const float4*)cur, (float4*)acc, (float4*)nxt);

    // Layer 3: nxt = A*cur; acc += nxt; zero cur
    spmm_kernel<<<grid_spmm, TB>>>(cur, nxt, adj_vals, rows, cols);
    add_zero_kernel<<<grid_full, TB>>>((const float4*)nxt, (float4*)acc, (float4*)cur);

    // Gathers
    gather_kernel<<<grid_gath, TB>>>((const float4*)user_table, (const float4*)group_table,
                                     user_inputs, pos_groups, neg_groups,
                                     (float4*)d_out);
}

// round 2
// speedup vs baseline: 2.3174x; 2.3174x over previous
#include <cuda_runtime.h>
#include <cuda_bf16.h>
#include <cstdint>

#define NUM_USER  200000
#define NUM_GROUP 50000
#define NROWS     (NUM_USER + NUM_GROUP)   // 250000
#define EDGES     4000000
#define DD        64
#define BB        8192

// ---- scratch (__device__ globals; no cudaMalloc allowed) -------------------
__device__ float g_a  [(size_t)NROWS * DD];     // 64 MB
__device__ float g_b  [(size_t)NROWS * DD];     // 64 MB
__device__ float g_acc[(size_t)NROWS * DD];     // 64 MB
__device__ int2  g_pairs[EDGES];                // 32 MB  (col, val-bits) sorted by row
__device__ int   g_counts[NROWS];
__device__ int   g_row_ptr[NROWS + 1];
__device__ int   g_cursor[NROWS];

#define SCAN_ELEMS 2048
#define NBLK_SCAN  ((NROWS + SCAN_ELEMS - 1) / SCAN_ELEMS)   // 123
__device__ int   g_blocksums[NBLK_SCAN];
__device__ int   g_blockoff [NBLK_SCAN];

// ---------------------------------------------------------------------------
// 1) zero histogram
__global__ __launch_bounds__(256)
void zero_counts_kernel()
{
    int i = blockIdx.x * blockDim.x + threadIdx.x;
    if (i < NROWS) g_counts[i] = 0;
}

// 2) histogram rows (int4-vectorized read)
__global__ __launch_bounds__(256)
void hist_kernel(const int4* __restrict__ rows4)
{
    int i = blockIdx.x * blockDim.x + threadIdx.x;
    if (i >= EDGES / 4) return;
    int4 r = rows4[i];
    atomicAdd(&g_counts[r.x], 1);
    atomicAdd(&g_counts[r.y], 1);
    atomicAdd(&g_counts[r.z], 1);
    atomicAdd(&g_counts[r.w], 1);
}

// 3a) per-block sums of counts
__global__ __launch_bounds__(256)
void scan1_kernel()
{
    __shared__ int sh[256];
    int tid  = threadIdx.x;
    int base = blockIdx.x * SCAN_ELEMS + tid * 8;
    int s = 0;
    #pragma unroll
    for (int j = 0; j < 8; j++) {
        int i = base + j;
        s += (i < NROWS) ? g_counts[i] : 0;
    }
    sh[tid] = s;
    __syncthreads();
    for (int off = 128; off > 0; off >>= 1) {
        if (tid < off) sh[tid] += sh[tid + off];
        __syncthreads();
    }
    if (tid == 0) g_blocksums[blockIdx.x] = sh[0];
}

// 3b) exclusive scan of 123 block sums (single thread — trivial)
__global__ void scan2_kernel()
{
    int run = 0;
    for (int b = 0; b < NBLK_SCAN; b++) {
        int t = g_blocksums[b];
        g_blockoff[b] = run;
        run += t;
    }
}

// 3c) intra-block exclusive scan + offset → row_ptr & cursor
__global__ __launch_bounds__(256)
void scan3_kernel()
{
    __shared__ int sh[256];
    int tid  = threadIdx.x;
    int base = blockIdx.x * SCAN_ELEMS + tid * 8;
    int v[8];
    int s = 0;
    #pragma unroll
    for (int j = 0; j < 8; j++) {
        int i = base + j;
        v[j] = (i < NROWS) ? g_counts[i] : 0;
        s += v[j];
    }
    sh[tid] = s;
    __syncthreads();
    // Hillis-Steele inclusive scan over 256 thread-totals
    for (int off = 1; off < 256; off <<= 1) {
        int t = (tid >= off) ? sh[tid - off] : 0;
        __syncthreads();
        sh[tid] += t;
        __syncthreads();
    }
    int excl = sh[tid] - s;
    int run  = g_blockoff[blockIdx.x] + excl;
    #pragma unroll
    for (int j = 0; j < 8; j++) {
        int i = base + j;
        if (i < NROWS) { g_row_ptr[i] = run; g_cursor[i] = run; }
        run += v[j];
    }
    if (blockIdx.x == 0 && tid == 0) g_row_ptr[NROWS] = EDGES;
}

// 4) scatter edges into row-sorted order
__global__ __launch_bounds__(256)
void scatter_kernel(const int* __restrict__ rows, const int* __restrict__ cols,
                    const float* __restrict__ vals)
{
    int e = blockIdx.x * blockDim.x + threadIdx.x;
    if (e >= EDGES) return;
    int r   = rows[e];
    int pos = atomicAdd(&g_cursor[r], 1);
    g_pairs[pos] = make_int2(cols[e], __float_as_int(vals[e]));
}

// ---------------------------------------------------------------------------
// 5) CSR spmm: 16 threads per row (one float4 lane each), register accumulate,
//    single store. Fused: dst[r]=s; acc[r] = (FIRST ? emb0[r] : acc[r]) + s.
// ---------------------------------------------------------------------------
template <bool FIRST>
__global__ __launch_bounds__(256)
void spmm_csr_kernel(const float4* __restrict__ su,   // src, user-index base
                     const float4* __restrict__ sg,   // src, group-index base
                     float4* __restrict__ dst,
                     float4* __restrict__ acc,
                     const float4* __restrict__ e0u,  // emb0 (layer 1 only)
                     const float4* __restrict__ e0g)
{
    int t    = blockIdx.x * blockDim.x + threadIdx.x;
    int r    = t >> 4;
    int lane = t & 15;
    if (r >= NROWS) return;

    int p  = g_row_ptr[r];
    int pe = g_row_ptr[r + 1];

    float4 a = make_float4(0.f, 0.f, 0.f, 0.f);

    // unroll by 2 for MLP
    for (; p + 2 <= pe; p += 2) {
        int2 q0 = __ldg(&g_pairs[p]);
        int2 q1 = __ldg(&g_pairs[p + 1]);
        const float4* b0 = (q0.x < NUM_USER) ? su + (size_t)q0.x * 16
                                             : sg + (size_t)(q0.x - NUM_USER) * 16;
        const float4* b1 = (q1.x < NUM_USER) ? su + (size_t)q1.x * 16
                                             : sg + (size_t)(q1.x - NUM_USER) * 16;
        float4 x0 = __ldg(b0 + lane);
        float4 x1 = __ldg(b1 + lane);
        float  v0 = __int_as_float(q0.y);
        float  v1 = __int_as_float(q1.y);
        a.x = fmaf(v1, x1.x, fmaf(v0, x0.x, a.x));
        a.y = fmaf(v1, x1.y, fmaf(v0, x0.y, a.y));
        a.z = fmaf(v1, x1.z, fmaf(v0, x0.z, a.z));
        a.w = fmaf(v1, x1.w, fmaf(v0, x0.w, a.w));
    }
    if (p < pe) {
        int2 q0 = __ldg(&g_pairs[p]);
        const float4* b0 = (q0.x < NUM_USER) ? su + (size_t)q0.x * 16
                                             : sg + (size_t)(q0.x - NUM_USER) * 16;
        float4 x0 = __ldg(b0 + lane);
        float  v0 = __int_as_float(q0.y);
        a.x = fmaf(v0, x0.x, a.x);
        a.y = fmaf(v0, x0.y, a.y);
        a.z = fmaf(v0, x0.z, a.z);
        a.w = fmaf(v0, x0.w, a.w);
    }

    size_t o = (size_t)r * 16 + lane;
    dst[o] = a;
    if (FIRST) {
        float4 e = (r < NUM_USER) ? e0u[(size_t)r * 16 + lane]
                                  : e0g[(size_t)(r - NUM_USER) * 16 + lane];
        acc[o] = make_float4(e.x + a.x, e.y + a.y, e.z + a.z, e.w + a.w);
    } else {
        float4 c = acc[o];
        acc[o] = make_float4(c.x + a.x, c.y + a.y, c.z + a.z, c.w + a.w);
    }
}

// ---------------------------------------------------------------------------
// 6) final six-way gather
// ---------------------------------------------------------------------------
__global__ __launch_bounds__(256)
void gather_kernel(const float4* __restrict__ ut, const float4* __restrict__ gt,
                   const int* __restrict__ ui, const int* __restrict__ pg,
                   const int* __restrict__ ng, float4* __restrict__ out)
{
    int t = blockIdx.x * blockDim.x + threadIdx.x;
    if (t >= BB * 16) return;
    int b    = t >> 4;
    int lane = t & 15;

    int u = ui[b];
    int p = pg[b];
    int n = ng[b];

    const float4* acc4 = reinterpret_cast<const float4*>(g_acc);
    float4 a0 = acc4[(size_t)u * 16 + lane];
    float4 a1 = acc4[((size_t)NUM_USER + p) * 16 + lane];
    float4 a2 = acc4[((size_t)NUM_USER + n) * 16 + lane];

    const float s = 0.25f;  // 1/(L+1)
    out[((size_t)0 * BB + b) * 16 + lane] = make_float4(a0.x*s, a0.y*s, a0.z*s, a0.w*s);
    out[((size_t)1 * BB + b) * 16 + lane] = make_float4(a1.x*s, a1.y*s, a1.z*s, a1.w*s);
    out[((size_t)2 * BB + b) * 16 + lane] = make_float4(a2.x*s, a2.y*s, a2.z*s, a2.w*s);
    out[((size_t)3 * BB + b) * 16 + lane] = ut[(size_t)u * 16 + lane];
    out[((size_t)4 * BB + b) * 16 + lane] = gt[(size_t)p * 16 + lane];
    out[((size_t)5 * BB + b) * 16 + lane] = gt[(size_t)n * 16 + lane];
}

// ---------------------------------------------------------------------------
extern "C" void kernel_launch(void* const* d_in, const int* in_sizes, int n_in,
                              void* d_out, int out_size)
{
    const float* user_table  = (const float*)d_in[0];
    const float* group_table = (const float*)d_in[1];
    const float* adj_vals    = (const float*)d_in[2];
    const int*   rows        = (const int*)  d_in[3];
    const int*   cols        = (const int*)  d_in[4];
    const int*   user_inputs = (const int*)  d_in[5];
    const int*   pos_groups  = (const int*)  d_in[6];
    const int*   neg_groups  = (const int*)  d_in[7];

    float* a = nullptr, * b = nullptr, * acc = nullptr;
    cudaGetSymbolAddress((void**)&a,   g_a);
    cudaGetSymbolAddress((void**)&b,   g_b);
    cudaGetSymbolAddress((void**)&acc, g_acc);

    const int TB = 256;

    // --- build CSR (counting sort by row) ---
    zero_counts_kernel<<<(NROWS + TB - 1) / TB, TB>>>();
    hist_kernel<<<(EDGES / 4 + TB - 1) / TB, TB>>>((const int4*)rows);
    scan1_kernel<<<NBLK_SCAN, TB>>>();
    scan2_kernel<<<1, 1>>>();
    scan3_kernel<<<NBLK_SCAN, TB>>>();
    scatter_kernel<<<(EDGES + TB - 1) / TB, TB>>>(rows, cols, adj_vals);

    const int grid_spmm = (NROWS * 16 + TB - 1) / TB;   // 15625

    const float4* ut4 = (const float4*)user_table;
    const float4* gt4 = (const float4*)group_table;

    // Layer 1: a = A*emb0 ; acc = emb0 + a     (src = concat tables)
    spmm_csr_kernel<true><<<grid_spmm, TB>>>(
        ut4, gt4, (float4*)a, (float4*)acc, ut4, gt4);

    // Layer 2: b = A*a ; acc += b
    spmm_csr_kernel<false><<<grid_spmm, TB>>>(
        (const float4*)a, (const float4*)(a + (size_t)NUM_USER * DD),
        (float4*)b, (float4*)acc, nullptr, nullptr);

    // Layer 3: a = A*b ; acc += a
    spmm_csr_kernel<false><<<grid_spmm, TB>>>(
        (const float4*)b, (const float4*)(b + (size_t)NUM_USER * DD),
        (float4*)a, (float4*)acc, nullptr, nullptr);

    // Gathers
    gather_kernel<<<(BB * 16 + TB - 1) / TB, TB>>>(
        ut4, gt4, user_inputs, pos_groups, neg_groups, (float4*)d_out);
}

// round 4
// speedup vs baseline: 3.6440x; 1.5724x over previous
#include <cuda_runtime.h>
#include <cuda_fp16.h>
#include <cstdint>

#define NUM_USER  200000
#define NUM_GROUP 50000
#define NROWS     (NUM_USER + NUM_GROUP)   // 250000
#define EDGES     4000000
#define DD        64
#define BB        8192

__device__ __forceinline__ int h2_as_int(__half2 h) {
    return *reinterpret_cast<int*>(&h);
}

// ---- scratch (__device__ globals; no cudaMalloc allowed) -------------------
// fp16 embedding buffers: 250000 x 64 halves = 32 MB each
__device__ __half g_e0[(size_t)NROWS * DD];   // fp16 copy of concat(tables)
__device__ __half g_e1[(size_t)NROWS * DD];
__device__ __half g_e2[(size_t)NROWS * DD];
__device__ __half g_e3[(size_t)NROWS * DD];
__device__ int2   g_pairs[EDGES];             // (col, val-bits) sorted by row
__device__ int    g_counts[NROWS];
__device__ int    g_row_ptr[NROWS + 1];
__device__ int    g_cursor[NROWS];

#define SCAN_ELEMS 2048
#define NBLK_SCAN  ((NROWS + SCAN_ELEMS - 1) / SCAN_ELEMS)   // 123
__device__ int   g_blocksums[NBLK_SCAN];
__device__ int   g_blockoff [NBLK_SCAN];

// ---------------------------------------------------------------------------
// 0) convert fp32 tables -> fp16 concat buffer (and zero histogram for free)
// ---------------------------------------------------------------------------
__global__ __launch_bounds__(256)
void convert_kernel(const float4* __restrict__ ut, const float4* __restrict__ gt)
{
    int i = blockIdx.x * blockDim.x + threadIdx.x;   // one int4 (8 halves) out
    if (i < NROWS) g_counts[i] = 0;
    if (i >= NROWS * 8) return;
    const int USER8 = NUM_USER * 8;
    float4 lo, hi;
    if (i < USER8) { lo = ut[(size_t)i * 2]; hi = ut[(size_t)i * 2 + 1]; }
    else { size_t j = i - USER8; lo = gt[j * 2]; hi = gt[j * 2 + 1]; }
    int4 o;
    o.x = h2_as_int(__floats2half2_rn(lo.x, lo.y));
    o.y = h2_as_int(__floats2half2_rn(lo.z, lo.w));
    o.z = h2_as_int(__floats2half2_rn(hi.x, hi.y));
    o.w = h2_as_int(__floats2half2_rn(hi.z, hi.w));
    reinterpret_cast<int4*>(g_e0)[i] = o;
}

// ---------------------------------------------------------------------------
// 1) histogram rows (int4-vectorized read)
// ---------------------------------------------------------------------------
__global__ __launch_bounds__(256)
void hist_kernel(const int4* __restrict__ rows4)
{
    int i = blockIdx.x * blockDim.x + threadIdx.x;
    if (i >= EDGES / 4) return;
    int4 r = rows4[i];
    atomicAdd(&g_counts[r.x], 1);
    atomicAdd(&g_counts[r.y], 1);
    atomicAdd(&g_counts[r.z], 1);
    atomicAdd(&g_counts[r.w], 1);
}

// ---------------------------------------------------------------------------
// 2a) per-block sums of counts
// ---------------------------------------------------------------------------
__global__ __launch_bounds__(256)
void scan1_kernel()
{
    __shared__ int sh[256];
    int tid  = threadIdx.x;
    int base = blockIdx.x * SCAN_ELEMS + tid * 8;
    int s = 0;
    #pragma unroll
    for (int j = 0; j < 8; j++) {
        int i = base + j;
        s += (i < NROWS) ? g_counts[i] : 0;
    }
    sh[tid] = s;
    __syncthreads();
    for (int off = 128; off > 0; off >>= 1) {
        if (tid < off) sh[tid] += sh[tid + off];
        __syncthreads();
    }
    if (tid == 0) g_blocksums[blockIdx.x] = sh[0];
}

// 2b) exclusive scan of 123 block sums (one block, parallel)
__global__ __launch_bounds__(128)
void scan2_kernel()
{
    __shared__ int sh[128];
    int tid = threadIdx.x;
    int v = (tid < NBLK_SCAN) ? g_blocksums[tid] : 0;
    sh[tid] = v;
    __syncthreads();
    for (int off = 1; off < 128; off <<= 1) {
        int t = (tid >= off) ? sh[tid - off] : 0;
        __syncthreads();
        sh[tid] += t;
        __syncthreads();
    }
    if (tid < NBLK_SCAN) g_blockoff[tid] = sh[tid] - v;
}

// 2c) intra-block exclusive scan + offset -> row_ptr & cursor
__global__ __launch_bounds__(256)
void scan3_kernel()
{
    __shared__ int sh[256];
    int tid  = threadIdx.x;
    int base = blockIdx.x * SCAN_ELEMS + tid * 8;
    int v[8];
    int s = 0;
    #pragma unroll
    for (int j = 0; j < 8; j++) {
        int i = base + j;
        v[j] = (i < NROWS) ? g_counts[i] : 0;
        s += v[j];
    }
    sh[tid] = s;
    __syncthreads();
    for (int off = 1; off < 256; off <<= 1) {
        int t = (tid >= off) ? sh[tid - off] : 0;
        __syncthreads();
        sh[tid] += t;
        __syncthreads();
    }
    int excl = sh[tid] - s;
    int run  = g_blockoff[blockIdx.x] + excl;
    #pragma unroll
    for (int j = 0; j < 8; j++) {
        int i = base + j;
        if (i < NROWS) { g_row_ptr[i] = run; g_cursor[i] = run; }
        run += v[j];
    }
    if (blockIdx.x == 0 && tid == 0) g_row_ptr[NROWS] = EDGES;
}

// ---------------------------------------------------------------------------
// 3) scatter edges into row-sorted order
// ---------------------------------------------------------------------------
__global__ __launch_bounds__(256)
void scatter_kernel(const int* __restrict__ rows, const int* __restrict__ cols,
                    const float* __restrict__ vals)
{
    int e = blockIdx.x * blockDim.x + threadIdx.x;
    if (e >= EDGES) return;
    int r   = rows[e];
    int pos = atomicAdd(&g_cursor[r], 1);
    g_pairs[pos] = make_int2(cols[e], __float_as_int(vals[e]));
}

// ---------------------------------------------------------------------------
// 4) CSR spmm, fp16 storage / fp32 accumulation.
//    8 threads per row; each owns 8 halves (one int4 / 16 B).
// ---------------------------------------------------------------------------
__device__ __forceinline__ void acc_fma8(float* a, int4 x, float v)
{
    __half2* h = reinterpret_cast<__half2*>(&x);
    #pragma unroll
    for (int i = 0; i < 4; i++) {
        float2 f = __half22float2(h[i]);
        a[2*i]   = fmaf(v, f.x, a[2*i]);
        a[2*i+1] = fmaf(v, f.y, a[2*i+1]);
    }
}

__global__ __launch_bounds__(256)
void spmm_csr_h_kernel(const int4* __restrict__ src, int4* __restrict__ dst)
{
    int t    = blockIdx.x * blockDim.x + threadIdx.x;
    int r    = t >> 3;
    int lane = t & 7;
    if (r >= NROWS) return;

    int p  = g_row_ptr[r];
    int pe = g_row_ptr[r + 1];

    float a[8];
    #pragma unroll
    for (int i = 0; i < 8; i++) a[i] = 0.f;

    for (; p + 2 <= pe; p += 2) {
        int2 q0 = __ldg(&g_pairs[p]);
        int2 q1 = __ldg(&g_pairs[p + 1]);
        int4 x0 = __ldg(&src[(size_t)q0.x * 8 + lane]);
        int4 x1 = __ldg(&src[(size_t)q1.x * 8 + lane]);
        acc_fma8(a, x0, __int_as_float(q0.y));
        acc_fma8(a, x1, __int_as_float(q1.y));
    }
    if (p < pe) {
        int2 q0 = __ldg(&g_pairs[p]);
        int4 x0 = __ldg(&src[(size_t)q0.x * 8 + lane]);
        acc_fma8(a, x0, __int_as_float(q0.y));
    }

    int4 o;
    o.x = h2_as_int(__floats2half2_rn(a[0], a[1]));
    o.y = h2_as_int(__floats2half2_rn(a[2], a[3]));
    o.z = h2_as_int(__floats2half2_rn(a[4], a[5]));
    o.w = h2_as_int(__floats2half2_rn(a[6], a[7]));
    dst[(size_t)r * 8 + lane] = o;
}

// ---------------------------------------------------------------------------
// 5) final six-way gather. acc computed on the fly: (emb0 + e1 + e2 + e3)/4.
//    16 threads per batch element; each owns 4 floats (uint2 of halves).
// ---------------------------------------------------------------------------
__device__ __forceinline__ float4 load_h4(const __half* base, size_t row, int lane)
{
    uint2 u = __ldg(reinterpret_cast<const uint2*>(base + row * DD) + lane);
    __half2 h0 = *reinterpret_cast<__half2*>(&u.x);
    __half2 h1 = *reinterpret_cast<__half2*>(&u.y);
    float2 f0 = __half22float2(h0);
    float2 f1 = __half22float2(h1);
    return make_float4(f0.x, f0.y, f1.x, f1.y);
}

__global__ __launch_bounds__(256)
void gather_kernel(const float4* __restrict__ ut, const float4* __restrict__ gt,
                   const int* __restrict__ ui, const int* __restrict__ pg,
                   const int* __restrict__ ng, float4* __restrict__ out)
{
    int t = blockIdx.x * blockDim.x + threadIdx.x;
    if (t >= BB * 16) return;
    int b    = t >> 4;
    int lane = t & 15;

    int u = ui[b];
    size_t gp = (size_t)NUM_USER + pg[b];
    size_t gn = (size_t)NUM_USER + ng[b];

    const float s = 0.25f;

    // user row
    {
        float4 t0 = ut[(size_t)u * 16 + lane];
        float4 f1 = load_h4(g_e1, (size_t)u, lane);
        float4 f2 = load_h4(g_e2, (size_t)u, lane);
        float4 f3 = load_h4(g_e3, (size_t)u, lane);
        out[((size_t)0 * BB + b) * 16 + lane] = make_float4(
            (t0.x + f1.x + f2.x + f3.x) * s, (t0.y + f1.y + f2.y + f3.y) * s,
            (t0.z + f1.z + f2.z + f3.z) * s, (t0.w + f1.w + f2.w + f3.w) * s);
        out[((size_t)3 * BB + b) * 16 + lane] = t0;
    }
    // pos group row
    {
        float4 t0 = gt[(gp - NUM_USER) * 16 + lane];
        float4 f1 = load_h4(g_e1, gp, lane);
        float4 f2 = load_h4(g_e2, gp, lane);
        float4 f3 = load_h4(g_e3, gp, lane);
        out[((size_t)1 * BB + b) * 16 + lane] = make_float4(
            (t0.x + f1.x + f2.x + f3.x) * s, (t0.y + f1.y + f2.y + f3.y) * s,
            (t0.z + f1.z + f2.z + f3.z) * s, (t0.w + f1.w + f2.w + f3.w) * s);
        out[((size_t)4 * BB + b) * 16 + lane] = t0;
    }
    // neg group row
    {
        float4 t0 = gt[(gn - NUM_USER) * 16 + lane];
        float4 f1 = load_h4(g_e1, gn, lane);
        float4 f2 = load_h4(g_e2, gn, lane);
        float4 f3 = load_h4(g_e3, gn, lane);
        out[((size_t)2 * BB + b) * 16 + lane] = make_float4(
            (t0.x + f1.x + f2.x + f3.x) * s, (t0.y + f1.y + f2.y + f3.y) * s,
            (t0.z + f1.z + f2.z + f3.z) * s, (t0.w + f1.w + f2.w + f3.w) * s);
        out[((size_t)5 * BB + b) * 16 + lane] = t0;
    }
}

// ---------------------------------------------------------------------------
extern "C" void kernel_launch(void* const* d_in, const int* in_sizes, int n_in,
                              void* d_out, int out_size)
{
    const float* user_table  = (const float*)d_in[0];
    const float* group_table = (const float*)d_in[1];
    const float* adj_vals    = (const float*)d_in[2];
    const int*   rows        = (const int*)  d_in[3];
    const int*   cols        = (const int*)  d_in[4];
    const int*   user_inputs = (const int*)  d_in[5];
    const int*   pos_groups  = (const int*)  d_in[6];
    const int*   neg_groups  = (const int*)  d_in[7];

    __half* e0 = nullptr, * e1 = nullptr, * e2 = nullptr, * e3 = nullptr;
    cudaGetSymbolAddress((void**)&e0, g_e0);
    cudaGetSymbolAddress((void**)&e1, g_e1);
    cudaGetSymbolAddress((void**)&e2, g_e2);
    cudaGetSymbolAddress((void**)&e3, g_e3);

    const int TB = 256;

    // fp32 tables -> fp16 concat (also zeroes histogram)
    convert_kernel<<<(NROWS * 8 + TB - 1) / TB, TB>>>(
        (const float4*)user_table, (const float4*)group_table);

    // CSR build (counting sort by row)
    hist_kernel<<<(EDGES / 4 + TB - 1) / TB, TB>>>((const int4*)rows);
    scan1_kernel<<<NBLK_SCAN, TB>>>();
    scan2_kernel<<<1, 128>>>();
    scan3_kernel<<<NBLK_SCAN, TB>>>();
    scatter_kernel<<<(EDGES + TB - 1) / TB, TB>>>(rows, cols, adj_vals);

    const int grid_spmm = (NROWS * 8 + TB - 1) / TB;   // 7813

    spmm_csr_h_kernel<<<grid_spmm, TB>>>((const int4*)e0, (int4*)e1);
    spmm_csr_h_kernel<<<grid_spmm, TB>>>((const int4*)e1, (int4*)e2);
    spmm_csr_h_kernel<<<grid_spmm, TB>>>((const int4*)e2, (int4*)e3);

    gather_kernel<<<(BB * 16 + TB - 1) / TB, TB>>>(
        (const float4*)user_table, (const float4*)group_table,
        user_inputs, pos_groups, neg_groups, (float4*)d_out);
}